// round 9
// baseline (speedup 1.0000x reference)
#include <cuda_runtime.h>
#include <math.h>

// Problem constants (fixed by the reference's setup_inputs)
#define NROWS   8192          // B
#define SLEN    4096          // S
#define NCHUNK  (SLEN / 32)   // 128 warp-iterations per row
#define PF      4             // prefetch depth (chunks in flight per warp)
#define BLOCK   64            // 2 warps/block: fine-grained wave scheduling

#define DELTA_T 900.0
// COOLING_SIGN = -1.0

__device__ __forceinline__ double bounded_d(double raw, double lo, double hi) {
    double s = 1.0 / (1.0 + exp(-raw));
    return lo + (hi - lo) * s;
}

// One warp per batch row. The recurrence t' = a*t + b_s has constant a,
// so 32 steps are resolved per iteration with a warp prefix-sum:
//   t_{lane} = a^{lane} * ( a * t_carry + sum_{j<=lane} a^{-j} * b_j )
// 4-chunk software pipeline keeps 4 independent coalesced 512B warp-loads
// in flight. 64-thread blocks: at 38 regs this gives 26 blocks/SM
// (52 warps, occ ~81%) and a 1/26-SM wave quantum, killing the R7
// low-occupancy tail (1024 blocks of 256 left a 136-block straggler wave
// running at 1 block/SM).
__global__ __launch_bounds__(BLOCK)
void rc_scan_kernel(const float4* __restrict__ in,
                    const float*  __restrict__ pR,
                    const float*  __restrict__ pC,
                    const float*  __restrict__ pA,
                    const float*  __restrict__ pG,
                    float*        __restrict__ out)
{
    const int gwarp = (blockIdx.x * BLOCK + threadIdx.x) >> 5;
    const int lane  = threadIdx.x & 31;
    if (gwarp >= NROWS) return;

    // --- scalar parameters (sigmoid-bounded), computed in double, negligible ---
    const double R = bounded_d((double)*pR, 1e-4, 0.2);
    const double C = bounded_d((double)*pC, 1e5, 1e8);
    const double A = bounded_d((double)*pA, 0.0, 0.2);
    const double G = bounded_d((double)*pG, 1.0, 20000.0);

    const double dtC = DELTA_T / C;
    const double a_d = 1.0 - dtC / R;       // ~0.9633 for given inputs
    const float  a   = (float)a_d;
    const float  kTo = (float)(dtC / R);    // coeff of t_out
    const float  kU  = (float)(-G * dtC);   // COOLING_SIGN * g * dt/C
    const float  kSo = (float)(A * dtC);    // coeff of solar

    const double la   = log(a_d);
    const float  apow = (float)exp(la * (double)lane);    // a^lane   (<=1)
    const float  ainv = (float)exp(-la * (double)lane);   // a^-lane  (<=~3.2)

    const float4* row  = in  + (size_t)gwarp * SLEN;  // 4 floats/step == one float4
    float*        orow = out + (size_t)gwarp * SLEN;

    // t_prev initial carry = t_in[b, 0] (channel 0 of step 0); broadcast load
    float t = __ldg((const float*)row);

    // Prime the 4-deep ring buffer: 4 independent coalesced loads in flight.
    float4 v[PF];
    #pragma unroll
    for (int k = 0; k < PF; k++)
        v[k] = row[k * 32 + lane];

    #pragma unroll 4
    for (int ch = 0; ch < NCHUNK; ch++) {
        // consume the oldest buffered chunk
        const float4 cur = v[ch & (PF - 1)];

        // refill that slot with chunk ch+PF (issued before the shfl chain,
        // so it overlaps the serial prefix + next 3 iterations)
        if (ch + PF < NCHUNK)
            v[ch & (PF - 1)] = row[(ch + PF) * 32 + lane];

        // b_s = kTo*t_out + kU*u + kSo*solar ; rescale for the prefix
        float b = fmaf(kTo, cur.y, fmaf(kU, cur.z, kSo * cur.w));
        float c = b * ainv;

        // inclusive warp prefix sum of c
        #pragma unroll
        for (int off = 1; off < 32; off <<= 1) {
            float n = __shfl_up_sync(0xffffffffu, c, off);
            if (lane >= off) c += n;
        }

        // t_lane = a^lane * (a * t_carry + prefix)
        float tv = apow * fmaf(a, t, c);
        orow[ch * 32 + lane] = tv;

        // carry out of this chunk = lane 31's value
        t = __shfl_sync(0xffffffffu, tv, 31);
    }
}

extern "C" void kernel_launch(void* const* d_in, const int* in_sizes, int n_in,
                              void* d_out, int out_size)
{
    (void)in_sizes; (void)n_in; (void)out_size;
    const float4* in = (const float4*)d_in[0];
    const float*  rR = (const float*)d_in[1];
    const float*  rC = (const float*)d_in[2];
    const float*  rA = (const float*)d_in[3];
    const float*  rG = (const float*)d_in[4];
    float* out = (float*)d_out;

    // one warp per row: 8192 warps, 2 warps (64 threads) per block
    dim3 grid(NROWS / (BLOCK / 32));
    dim3 block(BLOCK);
    rc_scan_kernel<<<grid, block>>>(in, rR, rC, rA, rG, out);
}

// round 13
// speedup vs baseline: 1.0023x; 1.0023x over previous
#include <cuda_runtime.h>
#include <math.h>

// Problem constants (fixed by the reference's setup_inputs)
#define NROWS   8192           // B
#define SLEN    4096           // S
#define NSUPER  (SLEN / 128)   // 32 super-chunks of 128 steps
#define BLOCK   64             // 2 warps per block

#define DELTA_T 900.0
// COOLING_SIGN = -1.0

__device__ __forceinline__ double bounded_d(double raw, double lo, double hi) {
    double s = 1.0 / (1.0 + exp(-raw));
    return lo + (hi - lo) * s;
}

// One warp per batch row; t' = a*t + b_s with constant a.
// R9 post-mortem: the binder was SHFL crossbar throughput (24 shuffles per
// 32-step chunk-round => ~94us structural floor). This version processes a
// 128-step super-chunk per round with a blocked K=4 scan:
//   - 4 coalesced float4 loads (unchanged pattern), b computed per step
//   - b staged through 512B smem to transpose ownership: lane l owns the 4
//     CONSECUTIVE steps 4l..4l+3 (STS.32 conflict-free; LDS.128 at 4*lane is
//     bank-conflict-free: each 8-lane phase spans all 32 banks)
//   - lane folds its 4 steps into one aggregate (3 FMAs), ONE 5-shuffle scan
//     over lane aggregates, 4 FMAs emit 4 outputs, one coalesced STG.128
// => 6 shuffles per 128 steps instead of 24: crossbar floor ~31us, DRAM binds.
__global__ __launch_bounds__(BLOCK)
void rc_scan_kernel(const float4* __restrict__ in,
                    const float*  __restrict__ pR,
                    const float*  __restrict__ pC,
                    const float*  __restrict__ pA,
                    const float*  __restrict__ pG,
                    float*        __restrict__ out)
{
    __shared__ __align__(16) float sbuf[2][2][128];  // [warp][buf][step]

    const int wib   = threadIdx.x >> 5;               // warp in block (0..1)
    const int gwarp = blockIdx.x * 2 + wib;           // row index
    const int lane  = threadIdx.x & 31;

    // --- scalar parameters (sigmoid-bounded), computed in double, negligible ---
    const double R = bounded_d((double)*pR, 1e-4, 0.2);
    const double C = bounded_d((double)*pC, 1e5, 1e8);
    const double A = bounded_d((double)*pA, 0.0, 0.2);
    const double G = bounded_d((double)*pG, 1.0, 20000.0);

    const double dtC = DELTA_T / C;
    const double a_d = 1.0 - dtC / R;       // ~0.9633 for given inputs
    const float  a   = (float)a_d;
    const float  kTo = (float)(dtC / R);    // coeff of t_out
    const float  kU  = (float)(-G * dtC);   // COOLING_SIGN * g * dt/C
    const float  kSo = (float)(A * dtC);    // coeff of solar

    const double la = log(a_d);
    const float ap4l   = (float)exp( la * (4.0 * lane));        // a^{4l}
    const float ainv4l = (float)exp(-la * (4.0 * lane));        // a^{-4l}
    const float ap4lm4 = (float)exp( la * (4.0 * lane - 4.0));  // a^{4l-4}

    const float4* row   = in + (size_t)gwarp * SLEN;   // 4 floats per step
    float4*       orow4 = (float4*)(out + (size_t)gwarp * SLEN);

    // initial carry = t_in[b, 0] (channel x of step 0)
    float t = __ldg((const float*)row);

    // prefetch super-chunk 0: lane l loads step 32j+l for j=0..3 (coalesced)
    float4 v0 = row[       lane];
    float4 v1 = row[ 32 + lane];
    float4 v2 = row[ 64 + lane];
    float4 v3 = row[ 96 + lane];

    for (int sc = 0; sc < NSUPER; sc++) {
        // forcing terms for the 4 owned (strided) steps
        float b0 = fmaf(kTo, v0.y, fmaf(kU, v0.z, kSo * v0.w));
        float b1 = fmaf(kTo, v1.y, fmaf(kU, v1.z, kSo * v1.w));
        float b2 = fmaf(kTo, v2.y, fmaf(kU, v2.z, kSo * v2.w));
        float b3 = fmaf(kTo, v3.y, fmaf(kU, v3.z, kSo * v3.w));

        // prefetch next super-chunk (a full round of cover before consumption)
        if (sc + 1 < NSUPER) {
            const float4* nrow = row + (sc + 1) * 128;
            v0 = nrow[      lane];
            v1 = nrow[ 32 + lane];
            v2 = nrow[ 64 + lane];
            v3 = nrow[ 96 + lane];
        }

        // transpose b ownership through smem: write step 32j+l, read 4l..4l+3
        float* sb = sbuf[wib][sc & 1];
        sb[      lane] = b0;
        sb[ 32 + lane] = b1;
        sb[ 64 + lane] = b2;
        sb[ 96 + lane] = b3;
        __syncwarp();
        const float4 bb = *(const float4*)(sb + 4 * lane);   // steps 4l..4l+3

        // local fold of 4 consecutive steps from zero carry:
        // loc = a^3*b0 + a^2*b1 + a*b2 + b3
        const float loc = fmaf(a, fmaf(a, fmaf(a, bb.x, bb.y), bb.z), bb.w);
        float h = loc * ainv4l;

        // ONE inclusive warp scan over lane aggregates
        float p = h;
        #pragma unroll
        for (int off = 1; off < 32; off <<= 1) {
            float n = __shfl_up_sync(0xffffffffu, p, off);
            if (lane >= off) p += n;
        }

        // carry entering this lane's block: T = a^{4l}*t + a^{4l-4}*(p - h)
        const float T = fmaf(ap4l, t, ap4lm4 * (p - h));

        // emit 4 consecutive outputs, store as one coalesced float4
        const float o0 = fmaf(a, T,  bb.x);
        const float o1 = fmaf(a, o0, bb.y);
        const float o2 = fmaf(a, o1, bb.z);
        const float o3 = fmaf(a, o2, bb.w);
        orow4[sc * 32 + lane] = make_float4(o0, o1, o2, o3);

        // carry out of the super-chunk = lane 31's last value
        t = __shfl_sync(0xffffffffu, o3, 31);
    }
}

extern "C" void kernel_launch(void* const* d_in, const int* in_sizes, int n_in,
                              void* d_out, int out_size)
{
    (void)in_sizes; (void)n_in; (void)out_size;
    const float4* in = (const float4*)d_in[0];
    const float*  rR = (const float*)d_in[1];
    const float*  rC = (const float*)d_in[2];
    const float*  rA = (const float*)d_in[3];
    const float*  rG = (const float*)d_in[4];
    float* out = (float*)d_out;

    // one warp per row: 8192 warps, 2 warps (64 threads) per block
    dim3 grid(NROWS / 2);
    dim3 block(BLOCK);
    rc_scan_kernel<<<grid, block>>>(in, rR, rC, rA, rG, out);
}